// round 7
// baseline (speedup 1.0000x reference)
#include <cuda_runtime.h>
#include <cstddef>

#define BB    2
#define NN    207
#define TT    12
#define FIN   64
#define HH    8
#define CDIM  8
#define HSTRIDE 12        // padded row stride (floats): 48B, conflict-free LDS.128
#define NWORDS 7          // ceil(207/32)
#define NCHUNK 3
#define RPC   69          // rows per chunk: 207 = 3*69
#define NGRP  35          // ceil(69/2) row-pair groups per chunk
#define LOG2E 1.4426950408889634f

__device__ __forceinline__ float ex2(float x) {
    float r;
    asm("ex2.approx.f32 %0, %1;" : "=f"(r) : "f"(x));
    return r;
}

// ---------------------------------------------------------------------------
// One fused kernel. grid = B*T*H*NCHUNK = 576, block = 256 (8 warps).
// leaky_0.2(x) = 0.6x + 0.4|x|  =>
// e[n,m] = p_n + p_m + sum_c (0.4 a_c)|h_n_c + h_m_c|,  p = sum_c 0.6 a_c h_c.
// All score terms prescaled by log2(e) so softmax uses bare ex2.approx.
// No-max softmax (scores are O(10); exp2 cannot overflow fp32).
// ---------------------------------------------------------------------------
__global__ void __launch_bounds__(256) k_fused(
    const float* __restrict__ X, const float* __restrict__ A,
    const float* __restrict__ W, const float* __restrict__ a_vec,
    float* __restrict__ out)
{
    __shared__ float    h_rm[NN * HSTRIDE];   // row-major h, 9.9 KB
    __shared__ float    p_sh[NN + 1];
    __shared__ unsigned msk[RPC * NWORDS];    // this chunk's adjacency bits
    __shared__ float    ws[FIN * CDIM];       // W column block for this head

    int bx    = blockIdx.x;
    int bth   = bx / NCHUNK;                  // (b*T+t)*H + hd
    int chunk = bx - bth * NCHUNK;
    int hd    = bth & 7;
    int bt    = bth >> 3;
    int t     = bt % TT;
    int b     = bt / TT;
    int tid   = threadIdx.x;
    int warp  = tid >> 5, lane = tid & 31;
    int n0    = chunk * RPC;

    float a4[CDIM];                           // 0.4 * a_c * log2(e)
#pragma unroll
    for (int c = 0; c < CDIM; c++) a4[c] = (0.4f * LOG2E) * __ldg(&a_vec[c]);

    // ---- adjacency bitmask for this chunk's 69 rows
    for (int p = warp; p < RPC * NWORDS; p += 8) {
        int row = p / NWORDS, k = p - row * NWORDS;
        int m = k * 32 + lane;
        bool v = (m < NN) && (A[(n0 + row) * NN + m] > 0.0f);
        unsigned bits = __ballot_sync(0xffffffffu, v);
        if (lane == 0) msk[p] = bits;
    }

    // ---- stage W[:, hd*8 .. hd*8+7]
    if (tid < 128) {
        int f = tid >> 1, half = tid & 1;
        *(float4*)&ws[f * CDIM + half * 4] =
            *(const float4*)&W[f * 64 + hd * CDIM + half * 4];
    }
    __syncthreads();

    // ---- per-block GEMM: thread n computes h[n][0..7]
    if (tid < NN) {
        int n = tid;
        const float* xr = X + ((size_t)(b * NN + n) * TT + t) * FIN;
        float acc[CDIM];
#pragma unroll
        for (int c = 0; c < CDIM; c++) acc[c] = 0.0f;
#pragma unroll
        for (int f = 0; f < FIN; f += 4) {
            float4 xv = *(const float4*)(xr + f);
            float xs4[4] = {xv.x, xv.y, xv.z, xv.w};
#pragma unroll
            for (int ff = 0; ff < 4; ff++) {
                float xs = xs4[ff];
                float4 w0 = *(float4*)&ws[(f + ff) * CDIM];
                float4 w1 = *(float4*)&ws[(f + ff) * CDIM + 4];
                acc[0] = fmaf(xs, w0.x, acc[0]);
                acc[1] = fmaf(xs, w0.y, acc[1]);
                acc[2] = fmaf(xs, w0.z, acc[2]);
                acc[3] = fmaf(xs, w0.w, acc[3]);
                acc[4] = fmaf(xs, w1.x, acc[4]);
                acc[5] = fmaf(xs, w1.y, acc[5]);
                acc[6] = fmaf(xs, w1.z, acc[6]);
                acc[7] = fmaf(xs, w1.w, acc[7]);
            }
        }
        float p = 0.0f;
#pragma unroll
        for (int c = 0; c < CDIM; c++) {
            h_rm[n * HSTRIDE + c] = acc[c];
            p = fmaf(1.5f * a4[c], acc[c], p);    // 0.6 a_c log2e = 1.5 * a4
        }
        p_sh[n] = p;
    }
    __syncthreads();

    // ---- attention: 35 groups x 2 rows, one group per warp per iteration
    for (int g = warp; g < NGRP; g += 8) {
        int  rl0 = 2 * g;
        int  r0  = n0 + rl0;
        bool v1  = (rl0 + 1) < RPC;
        int  r1  = v1 ? r0 + 1 : r0;
        int  rl1 = v1 ? rl0 + 1 : rl0;

        float hn0[CDIM], hn1[CDIM];
        {
            float4 u0 = *(float4*)&h_rm[r0 * HSTRIDE];
            float4 u1 = *(float4*)&h_rm[r0 * HSTRIDE + 4];
            hn0[0]=u0.x; hn0[1]=u0.y; hn0[2]=u0.z; hn0[3]=u0.w;
            hn0[4]=u1.x; hn0[5]=u1.y; hn0[6]=u1.z; hn0[7]=u1.w;
            float4 w0 = *(float4*)&h_rm[r1 * HSTRIDE];
            float4 w1 = *(float4*)&h_rm[r1 * HSTRIDE + 4];
            hn1[0]=w0.x; hn1[1]=w0.y; hn1[2]=w0.z; hn1[3]=w0.w;
            hn1[4]=w1.x; hn1[5]=w1.y; hn1[6]=w1.z; hn1[7]=w1.w;
        }
        float pn0 = p_sh[r0], pn1 = p_sh[r1];
        float s0 = 0.0f, s1 = 0.0f;

#pragma unroll
        for (int k = 0; k < NWORDS; k++) {
            int m  = k * 32 + lane;
            int mm = min(m, NN - 1);
            float4 m0 = *(float4*)&h_rm[mm * HSTRIDE];
            float4 m1 = *(float4*)&h_rm[mm * HSTRIDE + 4];
            float hm[CDIM] = {m0.x, m0.y, m0.z, m0.w, m1.x, m1.y, m1.z, m1.w};
            float pm = p_sh[mm];

            float q00 = 0.f, q01 = 0.f, q10 = 0.f, q11 = 0.f;
#pragma unroll
            for (int c = 0; c < CDIM; c++) {
                float x0 = hn0[c] + hm[c];
                float x1 = hn1[c] + hm[c];
                if (c & 1) { q01 = fmaf(a4[c], fabsf(x0), q01);
                             q11 = fmaf(a4[c], fabsf(x1), q11); }
                else       { q00 = fmaf(a4[c], fabsf(x0), q00);
                             q10 = fmaf(a4[c], fabsf(x1), q10); }
            }
            float ex0 = ex2(pn0 + pm + (q00 + q01));
            float ex1 = ex2(pn1 + pm + (q10 + q11));
            unsigned b0 = msk[rl0 * NWORDS + k];            // broadcast LDS
            unsigned b1 = msk[rl1 * NWORDS + k];
            s0 += ((b0 >> lane) & 1u) ? ex0 : 0.0f;
            s1 += ((b1 >> lane) & 1u) ? ex1 : 0.0f;
        }

#pragma unroll
        for (int off = 16; off; off >>= 1) {
            s0 += __shfl_xor_sync(0xffffffffu, s0, off);
            s1 += __shfl_xor_sync(0xffffffffu, s1, off);
        }

        // analytic diagonal + output
        float d0 = 0.f, d1 = 0.f;
#pragma unroll
        for (int c = 0; c < CDIM; c++) {
            d0 = fmaf(a4[c], fabsf(hn0[c]), d0);
            d1 = fmaf(a4[c], fabsf(hn1[c]), d1);
        }
        unsigned db0 = msk[rl0 * NWORDS + (r0 >> 5)];
        unsigned db1 = msk[rl1 * NWORDS + (r1 >> 5)];
        float att0 = ((db0 >> (r0 & 31)) & 1u)
                     ? __fdividef(ex2(2.0f * (pn0 + d0)), s0) : 0.0f;
        float att1 = ((db1 >> (r1 & 31)) & 1u)
                     ? __fdividef(ex2(2.0f * (pn1 + d1)), s1) : 0.0f;

        if (lane < CDIM) {
            out[((size_t)(b * NN + r0) * TT + t) * (HH * CDIM) + hd * CDIM + lane]
                = att0 * hn0[lane];
            if (v1)
                out[((size_t)(b * NN + r1) * TT + t) * (HH * CDIM) + hd * CDIM + lane]
                    = att1 * hn1[lane];
        }
    }
}

// ---------------------------------------------------------------------------
extern "C" void kernel_launch(void* const* d_in, const int* in_sizes, int n_in,
                              void* d_out, int out_size) {
    const float* X  = (const float*)d_in[0];   // (2,207,12,64)
    const float* A  = (const float*)d_in[1];   // (207,207)
    const float* W  = (const float*)d_in[2];   // (64,64)
    const float* av = (const float*)d_in[3];   // (8,)
    float* out = (float*)d_out;                // (2,207,12,64)

    k_fused<<<BB * TT * HH * NCHUNK, 256>>>(X, A, W, av, out);
}

// round 15
// speedup vs baseline: 1.0468x; 1.0468x over previous
#include <cuda_runtime.h>
#include <cstddef>

#define BB    2
#define NN    207
#define TT    12
#define FIN   64
#define HH    8
#define CDIM  8
#define HSTRIDE 12        // padded row stride (floats): 48B, conflict-free LDS.128
#define NWORDS 7          // ceil(207/32)
#define NCHUNK 3
#define RPC   69          // rows per chunk: 207 = 3*69
#define NGRP  35          // ceil(69/2) row-pair groups per chunk
#define LOG2E 1.4426950408889634f

__device__ __forceinline__ float ex2(float x) {
    float r;
    asm("ex2.approx.f32 %0, %1;" : "=f"(r) : "f"(x));
    return r;
}

// ---------------------------------------------------------------------------
// One fused kernel. grid = B*T*H*NCHUNK = 576, block = 256 (8 warps).
// leaky_0.2(x) = 0.6x + 0.4|x|  =>
// e[n,m] = p_n + p_m + sum_c (0.4 a_c)|h_n_c + h_m_c|,  p = sum_c 0.6 a_c h_c.
// Score terms prescaled by log2(e) -> bare ex2.approx; no-max online softmax.
// __launch_bounds__(256, 4) caps regs at 64 to stop ptxas front-batching the
// unrolled LDS.128 stream (R5/R7 regression root cause: 126 regs, occ 23%).
// All float4-accessed shared arrays are explicitly 16B-aligned (R14 crash fix).
// ---------------------------------------------------------------------------
__global__ void __launch_bounds__(256, 4) k_fused(
    const float* __restrict__ X, const float* __restrict__ A,
    const float* __restrict__ W, const float* __restrict__ a_vec,
    float* __restrict__ out)
{
    __shared__ __align__(16) float    h_rm[NN * HSTRIDE];   // row-major h, 9.9 KB
    __shared__ __align__(16) float    ws[FIN * CDIM];       // W column block
    __shared__ __align__(16) float    p_sh[NN + 1];
    __shared__ __align__(16) unsigned msk[RPC * NWORDS];    // adjacency bits

    int bx    = blockIdx.x;
    int bth   = bx / NCHUNK;                  // (b*T+t)*H + hd
    int chunk = bx - bth * NCHUNK;
    int hd    = bth & 7;
    int bt    = bth >> 3;
    int t     = bt % TT;
    int b     = bt / TT;
    int tid   = threadIdx.x;
    int warp  = tid >> 5, lane = tid & 31;
    int n0    = chunk * RPC;

    float a4[CDIM];                           // 0.4 * a_c * log2(e)
#pragma unroll
    for (int c = 0; c < CDIM; c++) a4[c] = (0.4f * LOG2E) * __ldg(&a_vec[c]);

    // ---- adjacency bitmask for this chunk's 69 rows
    for (int p = warp; p < RPC * NWORDS; p += 8) {
        int row = p / NWORDS, k = p - row * NWORDS;
        int m = k * 32 + lane;
        bool v = (m < NN) && (A[(n0 + row) * NN + m] > 0.0f);
        unsigned bits = __ballot_sync(0xffffffffu, v);
        if (lane == 0) msk[p] = bits;
    }

    // ---- stage W[:, hd*8 .. hd*8+7]
    if (tid < 128) {
        int f = tid >> 1, half = tid & 1;
        *(float4*)&ws[f * CDIM + half * 4] =
            *(const float4*)&W[f * 64 + hd * CDIM + half * 4];
    }
    __syncthreads();

    // ---- per-block GEMM: thread n computes h[n][0..7]
    if (tid < NN) {
        int n = tid;
        const float* xr = X + ((size_t)(b * NN + n) * TT + t) * FIN;
        float acc[CDIM];
#pragma unroll
        for (int c = 0; c < CDIM; c++) acc[c] = 0.0f;
#pragma unroll 4
        for (int f = 0; f < FIN; f += 4) {
            float4 xv = *(const float4*)(xr + f);
            float xs4[4] = {xv.x, xv.y, xv.z, xv.w};
#pragma unroll
            for (int ff = 0; ff < 4; ff++) {
                float xs = xs4[ff];
                float4 w0 = *(float4*)&ws[(f + ff) * CDIM];
                float4 w1 = *(float4*)&ws[(f + ff) * CDIM + 4];
                acc[0] = fmaf(xs, w0.x, acc[0]);
                acc[1] = fmaf(xs, w0.y, acc[1]);
                acc[2] = fmaf(xs, w0.z, acc[2]);
                acc[3] = fmaf(xs, w0.w, acc[3]);
                acc[4] = fmaf(xs, w1.x, acc[4]);
                acc[5] = fmaf(xs, w1.y, acc[5]);
                acc[6] = fmaf(xs, w1.z, acc[6]);
                acc[7] = fmaf(xs, w1.w, acc[7]);
            }
        }
        float p = 0.0f;
#pragma unroll
        for (int c = 0; c < CDIM; c++) {
            h_rm[n * HSTRIDE + c] = acc[c];
            p = fmaf(1.5f * a4[c], acc[c], p);    // 0.6 a_c log2e = 1.5 * a4
        }
        p_sh[n] = p;
    }
    __syncthreads();

    // ---- attention: 35 groups x 2 rows, one group per warp per iteration
    for (int g = warp; g < NGRP; g += 8) {
        int  rl0 = 2 * g;
        int  r0  = n0 + rl0;
        bool v1  = (rl0 + 1) < RPC;
        int  r1  = v1 ? r0 + 1 : r0;
        int  rl1 = v1 ? rl0 + 1 : rl0;

        float hn0[CDIM], hn1[CDIM];
        {
            float4 u0 = *(float4*)&h_rm[r0 * HSTRIDE];
            float4 u1 = *(float4*)&h_rm[r0 * HSTRIDE + 4];
            hn0[0]=u0.x; hn0[1]=u0.y; hn0[2]=u0.z; hn0[3]=u0.w;
            hn0[4]=u1.x; hn0[5]=u1.y; hn0[6]=u1.z; hn0[7]=u1.w;
            float4 w0 = *(float4*)&h_rm[r1 * HSTRIDE];
            float4 w1 = *(float4*)&h_rm[r1 * HSTRIDE + 4];
            hn1[0]=w0.x; hn1[1]=w0.y; hn1[2]=w0.z; hn1[3]=w0.w;
            hn1[4]=w1.x; hn1[5]=w1.y; hn1[6]=w1.z; hn1[7]=w1.w;
        }
        float pn0 = p_sh[r0], pn1 = p_sh[r1];
        float s0 = 0.0f, s1 = 0.0f;

#pragma unroll
        for (int k = 0; k < NWORDS; k++) {
            int m  = k * 32 + lane;
            int mm = min(m, NN - 1);
            float4 m0 = *(float4*)&h_rm[mm * HSTRIDE];
            float4 m1 = *(float4*)&h_rm[mm * HSTRIDE + 4];
            float hm[CDIM] = {m0.x, m0.y, m0.z, m0.w, m1.x, m1.y, m1.z, m1.w};
            float pm = p_sh[mm];

            float q00 = 0.f, q01 = 0.f, q10 = 0.f, q11 = 0.f;
#pragma unroll
            for (int c = 0; c < CDIM; c++) {
                float x0 = hn0[c] + hm[c];
                float x1 = hn1[c] + hm[c];
                if (c & 1) { q01 = fmaf(a4[c], fabsf(x0), q01);
                             q11 = fmaf(a4[c], fabsf(x1), q11); }
                else       { q00 = fmaf(a4[c], fabsf(x0), q00);
                             q10 = fmaf(a4[c], fabsf(x1), q10); }
            }
            float ex0 = ex2(pn0 + pm + (q00 + q01));
            float ex1 = ex2(pn1 + pm + (q10 + q11));
            unsigned b0 = msk[rl0 * NWORDS + k];            // broadcast LDS
            unsigned b1 = msk[rl1 * NWORDS + k];
            s0 += ((b0 >> lane) & 1u) ? ex0 : 0.0f;
            s1 += ((b1 >> lane) & 1u) ? ex1 : 0.0f;
        }

#pragma unroll
        for (int off = 16; off; off >>= 1) {
            s0 += __shfl_xor_sync(0xffffffffu, s0, off);
            s1 += __shfl_xor_sync(0xffffffffu, s1, off);
        }

        // analytic diagonal + output
        float d0 = 0.f, d1 = 0.f;
#pragma unroll
        for (int c = 0; c < CDIM; c++) {
            d0 = fmaf(a4[c], fabsf(hn0[c]), d0);
            d1 = fmaf(a4[c], fabsf(hn1[c]), d1);
        }
        unsigned db0 = msk[rl0 * NWORDS + (r0 >> 5)];
        unsigned db1 = msk[rl1 * NWORDS + (r1 >> 5)];
        float att0 = ((db0 >> (r0 & 31)) & 1u)
                     ? __fdividef(ex2(2.0f * (pn0 + d0)), s0) : 0.0f;
        float att1 = ((db1 >> (r1 & 31)) & 1u)
                     ? __fdividef(ex2(2.0f * (pn1 + d1)), s1) : 0.0f;

        if (lane < CDIM) {
            out[((size_t)(b * NN + r0) * TT + t) * (HH * CDIM) + hd * CDIM + lane]
                = att0 * hn0[lane];
            if (v1)
                out[((size_t)(b * NN + r1) * TT + t) * (HH * CDIM) + hd * CDIM + lane]
                    = att1 * hn1[lane];
        }
    }
}

// ---------------------------------------------------------------------------
extern "C" void kernel_launch(void* const* d_in, const int* in_sizes, int n_in,
                              void* d_out, int out_size) {
    const float* X  = (const float*)d_in[0];   // (2,207,12,64)
    const float* A  = (const float*)d_in[1];   // (207,207)
    const float* W  = (const float*)d_in[2];   // (64,64)
    const float* av = (const float*)d_in[3];   // (8,)
    float* out = (float*)d_out;                // (2,207,12,64)

    k_fused<<<BB * TT * HH * NCHUNK, 256>>>(X, A, W, av, out);
}